// round 4
// baseline (speedup 1.0000x reference)
#include <cuda_runtime.h>
#include <cuda_bf16.h>

// GCNConv: out = A_coo @ (X @ W) + bias
// Pipeline (5 launches):
//   K1 gemm   : support = X@W ; also zeroes g_count + scan lookback state
//   K2 hist   : per-dst degree histogram (int4-vectorized edge read)
//   K3 scan   : decoupled-lookback exclusive scan (packed 64-bit flag|value)
//   K4 build  : scatter edges into CSR buckets via cursor atomics
//   K5 spmm   : warp-per-row, register accumulation, 4x unrolled, bias folded
//
// Inputs (metadata order):
//   d_in[0] = x           float32 [N=100000, 64]
//   d_in[1] = edge_index  int32   [2, E=1600000]  (row 0 = dst, row 1 = src)
//   d_in[2] = edge_weight float32 [E]
//   d_in[3] = weight      float32 [64, 64]
//   d_in[4] = bias        float32 [64]
// Output: float32 [N, 64]

#define D_FEAT 64
#define MAX_N 100000
#define MAX_E 1600000
#define SCAN_BLK 1024
#define MAX_NB ((MAX_N + SCAN_BLK - 1) / SCAN_BLK + 1)   // 99

// Allocation-free scratch (__device__ globals)
__device__ float g_support[MAX_N * D_FEAT];          // 25.6 MB
__device__ int2  g_edges[MAX_E];                     // {src, w-as-int}, 12.8 MB
__device__ int   g_count[MAX_N];
__device__ int   g_rowptr[MAX_N + 1];
__device__ int   g_cursor[MAX_N];
// Packed lookback state: (flag << 32) | value.  flag: 0=none 1=aggregate 2=inclusive.
// Single 64-bit volatile store => flag and value can never be observed torn.
__device__ volatile unsigned long long g_blk_state[MAX_NB];

// ---------------------------------------------------------------------------
// K1: support = X @ W   (+ zero g_count, reset lookback state)
// 256 thr/block; each thread computes a 4-row x 16-col register tile.
// ---------------------------------------------------------------------------
__global__ __launch_bounds__(256) void gemm_xw_kernel(
    const float* __restrict__ x,
    const float* __restrict__ w,
    float* __restrict__ sup,
    int N, int NB)
{
    __shared__ float Ws[D_FEAT * D_FEAT];

    int tid = threadIdx.x;
    int gt  = blockIdx.x * 256 + tid;

    // fused housekeeping: zero histogram counters + scan state
    if (gt < N) g_count[gt] = 0;
    if (gt < NB) g_blk_state[gt] = 0ull;

    #pragma unroll
    for (int i = 0; i < 4; i++) {
        int idx = tid + i * 256;
        reinterpret_cast<float4*>(Ws)[idx] =
            reinterpret_cast<const float4*>(w)[idx];
    }
    __syncthreads();

    int cg  = tid & 3;
    int rg  = tid >> 2;
    int row0 = blockIdx.x * 256 + rg * 4;

    float acc[4][16];
    #pragma unroll
    for (int r = 0; r < 4; r++)
        #pragma unroll
        for (int c = 0; c < 16; c++)
            acc[r][c] = 0.0f;

    const int cbase = cg * 16;

    for (int k = 0; k < D_FEAT; k += 4) {
        float4 xv[4];
        #pragma unroll
        for (int r = 0; r < 4; r++) {
            int rr = row0 + r;
            xv[r] = (rr < N)
                ? *reinterpret_cast<const float4*>(x + (size_t)rr * D_FEAT + k)
                : make_float4(0.f, 0.f, 0.f, 0.f);
        }
        #pragma unroll
        for (int kk = 0; kk < 4; kk++) {
            float4 wv[4];
            #pragma unroll
            for (int j = 0; j < 4; j++)
                wv[j] = *reinterpret_cast<const float4*>(&Ws[(k + kk) * D_FEAT + cbase + j * 4]);
            #pragma unroll
            for (int r = 0; r < 4; r++) {
                float xs = (kk == 0) ? xv[r].x : (kk == 1) ? xv[r].y
                         : (kk == 2) ? xv[r].z : xv[r].w;
                #pragma unroll
                for (int j = 0; j < 4; j++) {
                    acc[r][j * 4 + 0] = fmaf(xs, wv[j].x, acc[r][j * 4 + 0]);
                    acc[r][j * 4 + 1] = fmaf(xs, wv[j].y, acc[r][j * 4 + 1]);
                    acc[r][j * 4 + 2] = fmaf(xs, wv[j].z, acc[r][j * 4 + 2]);
                    acc[r][j * 4 + 3] = fmaf(xs, wv[j].w, acc[r][j * 4 + 3]);
                }
            }
        }
    }

    #pragma unroll
    for (int r = 0; r < 4; r++) {
        int rr = row0 + r;
        if (rr < N) {
            #pragma unroll
            for (int j = 0; j < 4; j++) {
                float4 v = make_float4(acc[r][j * 4 + 0], acc[r][j * 4 + 1],
                                       acc[r][j * 4 + 2], acc[r][j * 4 + 3]);
                *reinterpret_cast<float4*>(sup + (size_t)rr * D_FEAT + cbase + j * 4) = v;
            }
        }
    }
}

// ---------------------------------------------------------------------------
// K2: histogram of dst degrees (4 edges per thread, int4 read)
// ---------------------------------------------------------------------------
__global__ __launch_bounds__(256) void hist_kernel(
    const int* __restrict__ edge_index, int E)
{
    int t = (blockIdx.x * 256 + threadIdx.x) * 4;
    if (t + 3 < E) {
        int4 d = *reinterpret_cast<const int4*>(edge_index + t);
        atomicAdd(&g_count[d.x], 1);
        atomicAdd(&g_count[d.y], 1);
        atomicAdd(&g_count[d.z], 1);
        atomicAdd(&g_count[d.w], 1);
    } else {
        for (int i = t; i < E; i++) atomicAdd(&g_count[edge_index[i]], 1);
    }
}

// ---------------------------------------------------------------------------
// K3: single-kernel exclusive scan, decoupled lookback with packed state.
// 98 blocks of 1024 — all resident simultaneously, spin-wait is safe.
// ---------------------------------------------------------------------------
__global__ __launch_bounds__(SCAN_BLK) void scan_kernel(int N, int E)
{
    __shared__ int wsum[32];
    __shared__ int s_base;

    int b = blockIdx.x;
    int i = b * SCAN_BLK + threadIdx.x;
    int c = (i < N) ? g_count[i] : 0;
    int lane = threadIdx.x & 31, wid = threadIdx.x >> 5;

    // block-local inclusive scan
    int v = c;
    #pragma unroll
    for (int o = 1; o < 32; o <<= 1) {
        int n = __shfl_up_sync(0xFFFFFFFFu, v, o);
        if (lane >= o) v += n;
    }
    if (lane == 31) wsum[wid] = v;
    __syncthreads();
    if (wid == 0) {
        int s = wsum[lane];
        #pragma unroll
        for (int o = 1; o < 32; o <<= 1) {
            int n = __shfl_up_sync(0xFFFFFFFFu, s, o);
            if (lane >= o) s += n;
        }
        wsum[lane] = s;
    }
    __syncthreads();

    int block_total = wsum[31];
    int local_incl  = v + ((wid > 0) ? wsum[wid - 1] : 0);

    // decoupled lookback (thread 0) — packed (flag|value) single-word protocol
    if (threadIdx.x == 0) {
        if (b == 0) {
            s_base = 0;
            g_blk_state[0] = (2ull << 32) | (unsigned)block_total;
        } else {
            g_blk_state[b] = (1ull << 32) | (unsigned)block_total;
            int excl = 0;
            int p = b - 1;
            while (true) {
                unsigned long long s;
                do { s = g_blk_state[p]; } while ((s >> 32) == 0ull);
                int val = (int)(unsigned)s;
                excl += val;
                if ((s >> 32) == 2ull) break;
                p--;
            }
            s_base = excl;
            g_blk_state[b] = (2ull << 32) | (unsigned)(excl + block_total);
        }
    }
    __syncthreads();

    int excl = s_base + local_incl - c;
    if (i < N) {
        g_rowptr[i] = excl;
        g_cursor[i] = excl;
        if (i == N - 1) g_rowptr[N] = E;
    }
}

// ---------------------------------------------------------------------------
// K4: scatter edges into CSR buckets
// ---------------------------------------------------------------------------
__global__ __launch_bounds__(256) void build_kernel(
    const int* __restrict__ edge_index,
    const float* __restrict__ edge_weight,
    int E)
{
    int t = blockIdx.x * 256 + threadIdx.x;
    if (t >= E) return;
    int dst = edge_index[t];
    int src = edge_index[E + t];
    float w = edge_weight[t];
    int pos = atomicAdd(&g_cursor[dst], 1);
    g_edges[pos] = make_int2(src, __float_as_int(w));
}

// ---------------------------------------------------------------------------
// K5: SpMM — one warp per dst row, lane owns 2 feats, 4x unroll for MLP.
// ---------------------------------------------------------------------------
__global__ __launch_bounds__(256) void spmm_kernel(
    const float* __restrict__ sup,
    const float* __restrict__ bias,
    float* __restrict__ out,
    int N)
{
    int t = blockIdx.x * 256 + threadIdx.x;
    int row = t >> 5;
    if (row >= N) return;
    int lane = t & 31;
    int f = lane * 2;

    float2 acc = *reinterpret_cast<const float2*>(bias + f);

    int beg = g_rowptr[row];
    int end = g_rowptr[row + 1];

    int j = beg;
    for (; j + 3 < end; j += 4) {
        int2 e0 = g_edges[j];
        int2 e1 = g_edges[j + 1];
        int2 e2 = g_edges[j + 2];
        int2 e3 = g_edges[j + 3];
        float2 v0 = *reinterpret_cast<const float2*>(sup + (size_t)e0.x * D_FEAT + f);
        float2 v1 = *reinterpret_cast<const float2*>(sup + (size_t)e1.x * D_FEAT + f);
        float2 v2 = *reinterpret_cast<const float2*>(sup + (size_t)e2.x * D_FEAT + f);
        float2 v3 = *reinterpret_cast<const float2*>(sup + (size_t)e3.x * D_FEAT + f);
        float w0 = __int_as_float(e0.y);
        float w1 = __int_as_float(e1.y);
        float w2 = __int_as_float(e2.y);
        float w3 = __int_as_float(e3.y);
        acc.x = fmaf(v0.x, w0, acc.x);  acc.y = fmaf(v0.y, w0, acc.y);
        acc.x = fmaf(v1.x, w1, acc.x);  acc.y = fmaf(v1.y, w1, acc.y);
        acc.x = fmaf(v2.x, w2, acc.x);  acc.y = fmaf(v2.y, w2, acc.y);
        acc.x = fmaf(v3.x, w3, acc.x);  acc.y = fmaf(v3.y, w3, acc.y);
    }
    for (; j < end; j++) {
        int2 e0 = g_edges[j];
        float2 v0 = *reinterpret_cast<const float2*>(sup + (size_t)e0.x * D_FEAT + f);
        float w0 = __int_as_float(e0.y);
        acc.x = fmaf(v0.x, w0, acc.x);
        acc.y = fmaf(v0.y, w0, acc.y);
    }

    *reinterpret_cast<float2*>(out + (size_t)row * D_FEAT + f) = acc;
}

// ---------------------------------------------------------------------------
extern "C" void kernel_launch(void* const* d_in, const int* in_sizes, int n_in,
                              void* d_out, int out_size)
{
    const float* x           = (const float*)d_in[0];
    const int*   edge_index  = (const int*)  d_in[1];
    const float* edge_weight = (const float*)d_in[2];
    const float* weight      = (const float*)d_in[3];
    const float* bias        = (const float*)d_in[4];
    float* out = (float*)d_out;

    const int N = in_sizes[0] / D_FEAT;
    const int E = in_sizes[2];
    const int NB = (N + SCAN_BLK - 1) / SCAN_BLK;

    float* sup = nullptr;
    cudaGetSymbolAddress((void**)&sup, g_support);

    gemm_xw_kernel<<<(N + 255) / 256, 256>>>(x, weight, sup, N, NB);
    hist_kernel<<<(E / 4 + 255) / 256, 256>>>(edge_index, E);
    scan_kernel<<<NB, SCAN_BLK>>>(N, E);
    build_kernel<<<(E + 255) / 256, 256>>>(edge_index, edge_weight, E);
    spmm_kernel<<<(N * 32 + 255) / 256, 256>>>(sup, bias, out, N);
}